// round 16
// baseline (speedup 1.0000x reference)
#include <cuda_runtime.h>
#include <math.h>

#define NB 256     // batch
#define DI 512     // input dim
#define HH 512     // hidden dim
#define H4 2048    // 4*H
#define H3 1536    // 3*H
#define EPSV 1.0f
#define NITER 3

// packed f32x2 FMA: d = (d.lo + a.lo*b.lo, d.hi + a.hi*b.hi)
#define FMA2(d, a, b) asm("fma.rn.f32x2 %0, %1, %2, %0;" : "+l"(d) : "l"(a), "l"(b))

// ---------------- scratch (static device globals; .bss => initially zero) ----------------
__device__ float g_Zp[4 * NB * H4];   // gemm_z partials (src x khalf)
__device__ float g_C3[NB * H3];       // gate coeffs ci,cf,cg
__device__ float g_u[NB * H3];        // u = C ⊙ p (GEMM A operand)
__device__ float g_diagA[NB * HH];    // Jacobi precond
__device__ float g_S6[6 * HH];        // W_a[j]·W_b[j] sym pairs
__device__ float g_r[NB * HH];        // CG residual
__device__ float g_p[NB * HH];        // CG direction
__device__ float g_t[NB * DI];        // t = G^T p, RED-accumulated (zeroed by gates/cg_update)
__device__ float g_vp[2 * NB * H3];   // k2 partials: (khalf)
__device__ float g_rz[NB];            // CG scalar r.z per batch

#define FMA16()                                                                                   \
    acc[0][0] += a4.x * b4.x; acc[0][1] += a4.x * b4.y; acc[0][2] += a4.x * b4.z; acc[0][3] += a4.x * b4.w; \
    acc[1][0] += a4.y * b4.x; acc[1][1] += a4.y * b4.y; acc[1][2] += a4.y * b4.z; acc[1][3] += a4.y * b4.w; \
    acc[2][0] += a4.z * b4.x; acc[2][1] += a4.z * b4.y; acc[2][2] += a4.z * b4.z; acc[2][3] += a4.z * b4.w; \
    acc[3][0] += a4.w * b4.x; acc[3][1] += a4.w * b4.y; acc[3][2] += a4.w * b4.z; acc[3][3] += a4.w * b4.w;

// ======== fused: gemm_z partials (z=0..3, STG) + S_ab (z=4) ========  [R12-identical]
// 128 thr; gemm tile 32(M)x64(N), K=256 ; grid (32, 8, 5)
__global__ __launch_bounds__(128) void gemm_z_kernel(const float* __restrict__ x, const float* __restrict__ hx,
                              const float* __restrict__ Wih, const float* __restrict__ Whh) {
    int tid = threadIdx.x;
    int zid = blockIdx.z;

    if (zid == 4) {
        int sub = tid >> 6;
        int lane = tid & 63;
        int j = ((blockIdx.y * 32 + blockIdx.x) << 1) | sub;   // 0..511
        const float* w0 = Wih + (0 * HH + j) * DI;
        const float* w1 = Wih + (1 * HH + j) * DI;
        const float* w2 = Wih + (2 * HH + j) * DI;
        float s[6] = {0.f, 0.f, 0.f, 0.f, 0.f, 0.f};
        for (int d = lane; d < DI; d += 64) {
            float a = w0[d], b = w1[d], c = w2[d];
            s[0] += a * a; s[1] += a * b; s[2] += a * c;
            s[3] += b * b; s[4] += b * c; s[5] += c * c;
        }
        __shared__ float red[2][2][6];
        int w = lane >> 5;
        #pragma unroll
        for (int q = 0; q < 6; q++) {
            float v = s[q];
            #pragma unroll
            for (int o = 16; o > 0; o >>= 1) v += __shfl_xor_sync(0xffffffffu, v, o);
            if ((lane & 31) == 0) red[sub][w][q] = v;
        }
        __syncthreads();
        if (lane == 0) {
            #pragma unroll
            for (int q = 0; q < 6; q++)
                g_S6[q * HH + j] = red[sub][0][q] + red[sub][1][q];
        }
        return;
    }

    __shared__ float As[2][16][36];
    __shared__ float Bs[2][16][68];
    int tx = tid % 16, ty = tid / 16;
    int lr = tid / 4, lc = (tid % 4) * 4;
    int br = tid / 2, bkc = (tid % 2) * 8;
    const float* A = (zid >> 1) ? hx : x;
    const float* B = (zid >> 1) ? Whh : Wih;
    int k0base = (zid & 1) * 256;
    int nbase = blockIdx.y * 32;
    int mbase = blockIdx.x * 64;
    float acc[4][4] = {};
    const float* Arow = A + (nbase + lr) * 512 + k0base;
    const float* Brow = B + (mbase + br) * 512 + k0base;

    {
        float4 ra = *(const float4*)(Arow + lc);
        As[0][lc + 0][lr] = ra.x; As[0][lc + 1][lr] = ra.y; As[0][lc + 2][lr] = ra.z; As[0][lc + 3][lr] = ra.w;
        float4 rb0 = *(const float4*)(Brow + bkc);
        float4 rb1 = *(const float4*)(Brow + bkc + 4);
        Bs[0][bkc + 0][br] = rb0.x; Bs[0][bkc + 1][br] = rb0.y; Bs[0][bkc + 2][br] = rb0.z; Bs[0][bkc + 3][br] = rb0.w;
        Bs[0][bkc + 4][br] = rb1.x; Bs[0][bkc + 5][br] = rb1.y; Bs[0][bkc + 6][br] = rb1.z; Bs[0][bkc + 7][br] = rb1.w;
    }
    __syncthreads();

    for (int s = 0; s < 16; s++) {
        int cur = s & 1;
        bool nx = (s + 1 < 16);
        float4 na, nb0, nb1;
        if (nx) {
            int k0 = (s + 1) * 16;
            na  = *(const float4*)(Arow + k0 + lc);
            nb0 = *(const float4*)(Brow + k0 + bkc);
            nb1 = *(const float4*)(Brow + k0 + bkc + 4);
        }
        #pragma unroll
        for (int kk = 0; kk < 16; kk++) {
            float4 a4 = *(const float4*)&As[cur][kk][ty * 4];
            float4 b4 = *(const float4*)&Bs[cur][kk][tx * 4];
            FMA16();
        }
        if (nx) {
            int nb_ = cur ^ 1;
            As[nb_][lc + 0][lr] = na.x; As[nb_][lc + 1][lr] = na.y; As[nb_][lc + 2][lr] = na.z; As[nb_][lc + 3][lr] = na.w;
            Bs[nb_][bkc + 0][br] = nb0.x; Bs[nb_][bkc + 1][br] = nb0.y; Bs[nb_][bkc + 2][br] = nb0.z; Bs[nb_][bkc + 3][br] = nb0.w;
            Bs[nb_][bkc + 4][br] = nb1.x; Bs[nb_][bkc + 5][br] = nb1.y; Bs[nb_][bkc + 6][br] = nb1.z; Bs[nb_][bkc + 7][br] = nb1.w;
        }
        __syncthreads();
    }
    float* outp = g_Zp + zid * (NB * H4);
    #pragma unroll
    for (int i = 0; i < 4; i++) {
        int row = nbase + ty * 4 + i;
        #pragma unroll
        for (int jj = 0; jj < 4; jj++) {
            outp[row * H4 + mbase + tx * 4 + jj] = acc[i][jj];
        }
    }
}

// ---------------- gates: activations, h_new, coeffs, diag, CG init; zero g_t ----------------
__global__ void gates_kernel(const float* __restrict__ cx,
                             const float* __restrict__ bih, const float* __restrict__ bhh,
                             float* __restrict__ out_h, float* __restrict__ out_x) {
    int n = blockIdx.x, j = threadIdx.x;  // 256 x 512
    const float* z0 = g_Zp + 0 * NB * H4 + n * H4;
    const float* z1 = g_Zp + 1 * NB * H4 + n * H4;
    const float* z2 = g_Zp + 2 * NB * H4 + n * H4;
    const float* z3 = g_Zp + 3 * NB * H4 + n * H4;
    #define ZSUM(o) (z0[o] + z1[o] + z2[o] + z3[o] + bih[o] + bhh[o])
    float zi = ZSUM(j);
    float zf = ZSUM(HH + j);
    float zg = ZSUM(2 * HH + j);
    float zo = ZSUM(3 * HH + j);
    float iv = 1.f / (1.f + expf(-zi));
    float fv = 1.f / (1.f + expf(-zf));
    float gv = tanhf(zg);
    float ov = 1.f / (1.f + expf(-zo));
    float cxv = cx[n * HH + j];
    float cn = fv * cxv + iv * gv;
    out_h[n * HH + j] = ov * tanhf(cn);

    float c0 = iv * (1.f - iv) * gv;
    float c1 = fv * (1.f - fv) * cxv;
    float c2 = (1.f - gv * gv) * iv;
    g_C3[n * H3 + j] = c0;
    g_C3[n * H3 + HH + j] = c1;
    g_C3[n * H3 + 2 * HH + j] = c2;

    float s00 = g_S6[j], s01 = g_S6[HH + j], s02 = g_S6[2 * HH + j];
    float s11 = g_S6[3 * HH + j], s12 = g_S6[4 * HH + j], s22 = g_S6[5 * HH + j];
    float dg = 1.f + EPSV * (c0 * c0 * s00 + c1 * c1 * s11 + c2 * c2 * s22 +
                             2.f * (c0 * c1 * s01 + c0 * c2 * s02 + c1 * c2 * s12));
    g_diagA[n * HH + j] = dg;

    out_x[n * HH + j] = 0.f;
    g_t[n * DI + j] = 0.f;              // zero accumulation target for first k1
    float rj = cn;
    float zj = rj / dg;
    g_r[n * HH + j] = rj;
    g_p[n * HH + j] = zj;
    g_u[n * H3 + j] = c0 * zj;
    g_u[n * H3 + HH + j] = c1 * zj;
    g_u[n * H3 + 2 * HH + j] = c2 * zj;

    __shared__ float red[512];
    red[j] = rj * zj;
    __syncthreads();
    for (int s = 256; s > 0; s >>= 1) {
        if (j < s) red[j] += red[j + s];
        __syncthreads();
    }
    if (j == 0) g_rz[n] = red[0];
}

// ======== k1: g_t += u-slice @ W-slice (NN) via RED.ADD ; f32x2 packed inner ========
// 128 thr, tile 32x64, K=256 ; grid (8, 8, 6) -> 384 CTAs
__global__ __launch_bounds__(128) void k1_kernel(const float* __restrict__ Wih) {
    __shared__ __align__(16) float As[2][16][36];
    __shared__ __align__(16) float Bs[2][16][136];   // B duplicated: [2j]=[2j+1]=b_j
    int tid = threadIdx.x;
    int tx = tid % 16, ty = tid / 16;
    int lr = tid / 4, lc = (tid % 4) * 4;
    int bkr = tid / 16, bc = (tid % 16) * 4;    // B (NN): k-rows bkr, bkr+8
    int zid = blockIdx.z;
    int gate = zid >> 1, kh = zid & 1;
    int jbase = gate * HH + kh * 256;
    int nbase = blockIdx.y * 32;
    int dbase = blockIdx.x * 64;
    unsigned long long accP[2][4] = {};         // [ipair][j]: (acc[2p][j], acc[2p+1][j])

    const float* Arow = g_u + (nbase + lr) * H3 + jbase;
    const float* Bb = Wih + jbase * DI + dbase;

    {
        float4 ra = *(const float4*)(Arow + lc);
        As[0][lc + 0][lr] = ra.x; As[0][lc + 1][lr] = ra.y; As[0][lc + 2][lr] = ra.z; As[0][lc + 3][lr] = ra.w;
        float4 rb0 = *(const float4*)(Bb + bkr * DI + bc);
        float4 rb1 = *(const float4*)(Bb + (bkr + 8) * DI + bc);
        *(float4*)&Bs[0][bkr][2 * bc]         = make_float4(rb0.x, rb0.x, rb0.y, rb0.y);
        *(float4*)&Bs[0][bkr][2 * bc + 4]     = make_float4(rb0.z, rb0.z, rb0.w, rb0.w);
        *(float4*)&Bs[0][bkr + 8][2 * bc]     = make_float4(rb1.x, rb1.x, rb1.y, rb1.y);
        *(float4*)&Bs[0][bkr + 8][2 * bc + 4] = make_float4(rb1.z, rb1.z, rb1.w, rb1.w);
    }
    __syncthreads();

    for (int s = 0; s < 16; s++) {
        int cur = s & 1;
        bool nx = (s + 1 < 16);
        float4 na, nb0, nb1;
        if (nx) {
            int k0 = (s + 1) * 16;
            na  = *(const float4*)(Arow + k0 + lc);
            nb0 = *(const float4*)(Bb + (k0 + bkr) * DI + bc);
            nb1 = *(const float4*)(Bb + (k0 + bkr + 8) * DI + bc);
        }
        #pragma unroll
        for (int kk = 0; kk < 16; kk++) {
            ulonglong2 av  = *(const ulonglong2*)&As[cur][kk][ty * 4];        // (a0,a1),(a2,a3)
            ulonglong2 b01 = *(const ulonglong2*)&Bs[cur][kk][tx * 8];        // (b0,b0),(b1,b1)
            ulonglong2 b23 = *(const ulonglong2*)&Bs[cur][kk][tx * 8 + 4];    // (b2,b2),(b3,b3)
            FMA2(accP[0][0], av.x, b01.x); FMA2(accP[1][0], av.y, b01.x);
            FMA2(accP[0][1], av.x, b01.y); FMA2(accP[1][1], av.y, b01.y);
            FMA2(accP[0][2], av.x, b23.x); FMA2(accP[1][2], av.y, b23.x);
            FMA2(accP[0][3], av.x, b23.y); FMA2(accP[1][3], av.y, b23.y);
        }
        if (nx) {
            int nbuf = cur ^ 1;
            As[nbuf][lc + 0][lr] = na.x; As[nbuf][lc + 1][lr] = na.y; As[nbuf][lc + 2][lr] = na.z; As[nbuf][lc + 3][lr] = na.w;
            *(float4*)&Bs[nbuf][bkr][2 * bc]         = make_float4(nb0.x, nb0.x, nb0.y, nb0.y);
            *(float4*)&Bs[nbuf][bkr][2 * bc + 4]     = make_float4(nb0.z, nb0.z, nb0.w, nb0.w);
            *(float4*)&Bs[nbuf][bkr + 8][2 * bc]     = make_float4(nb1.x, nb1.x, nb1.y, nb1.y);
            *(float4*)&Bs[nbuf][bkr + 8][2 * bc + 4] = make_float4(nb1.z, nb1.z, nb1.w, nb1.w);
        }
        __syncthreads();
    }
    #pragma unroll
    for (int p = 0; p < 2; p++) {
        #pragma unroll
        for (int i2 = 0; i2 < 2; i2++) {
            int row = nbase + ty * 4 + p * 2 + i2;
            float* tr = g_t + row * DI + dbase + tx * 4;
            atomicAdd(tr + 0, ((const float*)&accP[p][0])[i2]);
            atomicAdd(tr + 1, ((const float*)&accP[p][1])[i2]);
            atomicAdd(tr + 2, ((const float*)&accP[p][2])[i2]);
            atomicAdd(tr + 3, ((const float*)&accP[p][3])[i2]);
        }
    }
}

// ======== k2: vp[kh] = t @ W3^T-slice (NT) ; f32x2 packed inner ========
// 128 thr, tile 32x64, K=256 ; grid (24, 8, 2) -> 384 CTAs
__global__ __launch_bounds__(128) void k2_kernel(const float* __restrict__ Wih) {
    __shared__ __align__(16) float As[2][16][36];
    __shared__ __align__(16) float Bs[2][16][136];   // B duplicated: [2j]=[2j+1]=b_j
    int tid = threadIdx.x;
    int tx = tid % 16, ty = tid / 16;
    int lr = tid / 4, lc = (tid % 4) * 4;
    int br = tid / 2, bkc = (tid % 2) * 8;
    int kh = blockIdx.z;
    int dbase0 = kh * 256;
    int nbase = blockIdx.y * 32;
    int mbase = blockIdx.x * 64;
    unsigned long long accP[2][4] = {};

    const float* T = g_t + (nbase + lr) * DI + dbase0;
    const float* Brow = Wih + (mbase + br) * DI + dbase0;

    {
        float4 ta = *(const float4*)(T + lc);
        As[0][lc + 0][lr] = ta.x; As[0][lc + 1][lr] = ta.y; As[0][lc + 2][lr] = ta.z; As[0][lc + 3][lr] = ta.w;
        float4 rb0 = *(const float4*)(Brow + bkc);
        float4 rb1 = *(const float4*)(Brow + bkc + 4);
        *(float2*)&Bs[0][bkc + 0][2 * br] = make_float2(rb0.x, rb0.x);
        *(float2*)&Bs[0][bkc + 1][2 * br] = make_float2(rb0.y, rb0.y);
        *(float2*)&Bs[0][bkc + 2][2 * br] = make_float2(rb0.z, rb0.z);
        *(float2*)&Bs[0][bkc + 3][2 * br] = make_float2(rb0.w, rb0.w);
        *(float2*)&Bs[0][bkc + 4][2 * br] = make_float2(rb1.x, rb1.x);
        *(float2*)&Bs[0][bkc + 5][2 * br] = make_float2(rb1.y, rb1.y);
        *(float2*)&Bs[0][bkc + 6][2 * br] = make_float2(rb1.z, rb1.z);
        *(float2*)&Bs[0][bkc + 7][2 * br] = make_float2(rb1.w, rb1.w);
    }
    __syncthreads();

    for (int s = 0; s < 16; s++) {
        int cur = s & 1;
        bool nx = (s + 1 < 16);
        float4 ta, nb0, nb1;
        if (nx) {
            int k0 = (s + 1) * 16;
            ta  = *(const float4*)(T + k0 + lc);
            nb0 = *(const float4*)(Brow + k0 + bkc);
            nb1 = *(const float4*)(Brow + k0 + bkc + 4);
        }
        #pragma unroll
        for (int kk = 0; kk < 16; kk++) {
            ulonglong2 av  = *(const ulonglong2*)&As[cur][kk][ty * 4];
            ulonglong2 b01 = *(const ulonglong2*)&Bs[cur][kk][tx * 8];
            ulonglong2 b23 = *(const ulonglong2*)&Bs[cur][kk][tx * 8 + 4];
            FMA2(accP[0][0], av.x, b01.x); FMA2(accP[1][0], av.y, b01.x);
            FMA2(accP[0][1], av.x, b01.y); FMA2(accP[1][1], av.y, b01.y);
            FMA2(accP[0][2], av.x, b23.x); FMA2(accP[1][2], av.y, b23.x);
            FMA2(accP[0][3], av.x, b23.y); FMA2(accP[1][3], av.y, b23.y);
        }
        if (nx) {
            int nbuf = cur ^ 1;
            As[nbuf][lc + 0][lr] = ta.x; As[nbuf][lc + 1][lr] = ta.y; As[nbuf][lc + 2][lr] = ta.z; As[nbuf][lc + 3][lr] = ta.w;
            *(float2*)&Bs[nbuf][bkc + 0][2 * br] = make_float2(nb0.x, nb0.x);
            *(float2*)&Bs[nbuf][bkc + 1][2 * br] = make_float2(nb0.y, nb0.y);
            *(float2*)&Bs[nbuf][bkc + 2][2 * br] = make_float2(nb0.z, nb0.z);
            *(float2*)&Bs[nbuf][bkc + 3][2 * br] = make_float2(nb0.w, nb0.w);
            *(float2*)&Bs[nbuf][bkc + 4][2 * br] = make_float2(nb1.x, nb1.x);
            *(float2*)&Bs[nbuf][bkc + 5][2 * br] = make_float2(nb1.y, nb1.y);
            *(float2*)&Bs[nbuf][bkc + 6][2 * br] = make_float2(nb1.z, nb1.z);
            *(float2*)&Bs[nbuf][bkc + 7][2 * br] = make_float2(nb1.w, nb1.w);
        }
        __syncthreads();
    }
    float* outp = g_vp + kh * (NB * H3);
    #pragma unroll
    for (int p = 0; p < 2; p++) {
        #pragma unroll
        for (int i2 = 0; i2 < 2; i2++) {
            int row = nbase + ty * 4 + p * 2 + i2;
            float* vr = outp + row * H3 + mbase + tx * 4;
            vr[0] = ((const float*)&accP[p][0])[i2];
            vr[1] = ((const float*)&accP[p][1])[i2];
            vr[2] = ((const float*)&accP[p][2])[i2];
            vr[3] = ((const float*)&accP[p][3])[i2];
        }
    }
}

// ---------------- full PCG update (non-final iterations); re-zeroes g_t ----------------
__global__ __launch_bounds__(256) void cg_update_kernel(float* __restrict__ out_x) {
    int n = blockIdx.x;
    int t = threadIdx.x;
    int j0 = t, j1 = t + 256;
    __shared__ float warpsum[8];
    __shared__ float s_scalar;

    const float* v0 = g_vp + n * H3;
    const float* v1 = g_vp + NB * H3 + n * H3;
    const float* C = g_C3 + n * H3;

    // zero g_t for the next k1 accumulation (t consumed by k2 already)
    g_t[n * DI + j0] = 0.f;
    g_t[n * DI + j1] = 0.f;

    float p0 = g_p[n * HH + j0], p1 = g_p[n * HH + j1];
    float c00 = C[j0], c10 = C[HH + j0], c20 = C[2 * HH + j0];
    float c01 = C[j1], c11 = C[HH + j1], c21 = C[2 * HH + j1];
    float gp0 = c00 * (v0[j0] + v1[j0]) + c10 * (v0[HH + j0] + v1[HH + j0]) + c20 * (v0[2 * HH + j0] + v1[2 * HH + j0]);
    float gp1 = c01 * (v0[j1] + v1[j1]) + c11 * (v0[HH + j1] + v1[HH + j1]) + c21 * (v0[2 * HH + j1] + v1[2 * HH + j1]);
    float Ap0 = p0 + EPSV * gp0;
    float Ap1 = p1 + EPSV * gp1;

    float part = p0 * Ap0 + p1 * Ap1;
    #pragma unroll
    for (int o = 16; o > 0; o >>= 1) part += __shfl_xor_sync(0xffffffffu, part, o);
    if ((t & 31) == 0) warpsum[t >> 5] = part;
    __syncthreads();
    if (t < 8) {
        float v = warpsum[t];
        #pragma unroll
        for (int o = 4; o > 0; o >>= 1) v += __shfl_xor_sync(0xffu, v, o);
        if (t == 0) s_scalar = v;
    }
    __syncthreads();
    float rzold = g_rz[n];
    float alpha = rzold / fmaxf(s_scalar, 1e-30f);

    float x0 = out_x[n * HH + j0] + alpha * p0;
    float x1 = out_x[n * HH + j1] + alpha * p1;
    float r0 = g_r[n * HH + j0] - alpha * Ap0;
    float r1 = g_r[n * HH + j1] - alpha * Ap1;
    float z0 = r0 / g_diagA[n * HH + j0];
    float z1 = r1 / g_diagA[n * HH + j1];

    __syncthreads();
    part = r0 * z0 + r1 * z1;
    #pragma unroll
    for (int o = 16; o > 0; o >>= 1) part += __shfl_xor_sync(0xffffffffu, part, o);
    if ((t & 31) == 0) warpsum[t >> 5] = part;
    __syncthreads();
    if (t < 8) {
        float v = warpsum[t];
        #pragma unroll
        for (int o = 4; o > 0; o >>= 1) v += __shfl_xor_sync(0xffu, v, o);
        if (t == 0) { s_scalar = v; g_rz[n] = v; }
    }
    __syncthreads();
    float beta = s_scalar / fmaxf(rzold, 1e-30f);

    float pn0 = z0 + beta * p0;
    float pn1 = z1 + beta * p1;
    out_x[n * HH + j0] = x0;  out_x[n * HH + j1] = x1;
    g_r[n * HH + j0] = r0;    g_r[n * HH + j1] = r1;
    g_p[n * HH + j0] = pn0;   g_p[n * HH + j1] = pn1;
    float* U = g_u + n * H3;
    U[j0] = c00 * pn0;           U[j1] = c01 * pn1;
    U[HH + j0] = c10 * pn0;      U[HH + j1] = c11 * pn1;
    U[2 * HH + j0] = c20 * pn0;  U[2 * HH + j1] = c21 * pn1;
}

// ---------------- final PCG step: only alpha + x update ----------------
__global__ __launch_bounds__(256) void cg_final_kernel(float* __restrict__ out_x) {
    int n = blockIdx.x;
    int t = threadIdx.x;
    int j0 = t, j1 = t + 256;
    __shared__ float warpsum[8];
    __shared__ float s_scalar;

    const float* v0 = g_vp + n * H3;
    const float* v1 = g_vp + NB * H3 + n * H3;
    const float* C = g_C3 + n * H3;

    float p0 = g_p[n * HH + j0], p1 = g_p[n * HH + j1];
    float c00 = C[j0], c10 = C[HH + j0], c20 = C[2 * HH + j0];
    float c01 = C[j1], c11 = C[HH + j1], c21 = C[2 * HH + j1];
    float gp0 = c00 * (v0[j0] + v1[j0]) + c10 * (v0[HH + j0] + v1[HH + j0]) + c20 * (v0[2 * HH + j0] + v1[2 * HH + j0]);
    float gp1 = c01 * (v0[j1] + v1[j1]) + c11 * (v0[HH + j1] + v1[HH + j1]) + c21 * (v0[2 * HH + j1] + v1[2 * HH + j1]);
    float Ap0 = p0 + EPSV * gp0;
    float Ap1 = p1 + EPSV * gp1;

    float part = p0 * Ap0 + p1 * Ap1;
    #pragma unroll
    for (int o = 16; o > 0; o >>= 1) part += __shfl_xor_sync(0xffffffffu, part, o);
    if ((t & 31) == 0) warpsum[t >> 5] = part;
    __syncthreads();
    if (t < 8) {
        float v = warpsum[t];
        #pragma unroll
        for (int o = 4; o > 0; o >>= 1) v += __shfl_xor_sync(0xffu, v, o);
        if (t == 0) s_scalar = v;
    }
    __syncthreads();
    float alpha = g_rz[n] / fmaxf(s_scalar, 1e-30f);

    out_x[n * HH + j0] += alpha * p0;
    out_x[n * HH + j1] += alpha * p1;
}

// ---------------- launch ----------------
extern "C" void kernel_launch(void* const* d_in, const int* in_sizes, int n_in,
                              void* d_out, int out_size) {
    const float* x   = (const float*)d_in[0];
    const float* hx  = (const float*)d_in[1];
    const float* cx  = (const float*)d_in[2];
    const float* Wih = (const float*)d_in[3];
    const float* Whh = (const float*)d_in[4];
    const float* bih = (const float*)d_in[5];
    const float* bhh = (const float*)d_in[6];
    float* out_h = (float*)d_out;
    float* out_x = out_h + NB * HH;

    gemm_z_kernel<<<dim3(H4 / 64, NB / 32, 5), 128>>>(x, hx, Wih, Whh);
    gates_kernel<<<NB, HH>>>(cx, bih, bhh, out_h, out_x);

    for (int it = 0; it < NITER; it++) {
        k1_kernel<<<dim3(DI / 64, NB / 32, 6), 128>>>(Wih);
        k2_kernel<<<dim3(H3 / 64, NB / 32, 2), 128>>>(Wih);
        if (it < NITER - 1)
            cg_update_kernel<<<NB, 256>>>(out_x);
        else
            cg_final_kernel<<<NB, 256>>>(out_x);
    }
}

// round 17
// speedup vs baseline: 1.9585x; 1.9585x over previous
#include <cuda_runtime.h>
#include <math.h>

#define NB 256     // batch
#define DI 512     // input dim
#define HH 512     // hidden dim
#define H4 2048    // 4*H
#define H3 1536    // 3*H
#define EPSV 1.0f
#define NITER 3

// ---------------- scratch (static device globals; .bss => initially zero) ----------------
__device__ float g_Zp[4 * NB * H4];   // gemm_z partials (src x khalf)
__device__ float g_C3[NB * H3];       // gate coeffs ci,cf,cg
__device__ float g_u[NB * H3];        // u = C ⊙ p (GEMM A operand)
__device__ float g_diagA[NB * HH];    // Jacobi precond
__device__ float g_S6[6 * HH];        // W_a[j]·W_b[j] sym pairs
__device__ float g_r[NB * HH];        // CG residual
__device__ float g_p[NB * HH];        // CG direction
__device__ float g_t[NB * DI];        // t = G^T p, RED-accumulated (zeroed by gates/cg_update)
__device__ float g_vp[2 * NB * H3];   // k2 partials: (khalf)
__device__ float g_rz[NB];            // CG scalar r.z per batch

#define FMA16()                                                                                   \
    acc[0][0] += a4.x * b4.x; acc[0][1] += a4.x * b4.y; acc[0][2] += a4.x * b4.z; acc[0][3] += a4.x * b4.w; \
    acc[1][0] += a4.y * b4.x; acc[1][1] += a4.y * b4.y; acc[1][2] += a4.y * b4.z; acc[1][3] += a4.y * b4.w; \
    acc[2][0] += a4.z * b4.x; acc[2][1] += a4.z * b4.y; acc[2][2] += a4.z * b4.z; acc[2][3] += a4.z * b4.w; \
    acc[3][0] += a4.w * b4.x; acc[3][1] += a4.w * b4.y; acc[3][2] += a4.w * b4.z; acc[3][3] += a4.w * b4.w;

// ======== fused: gemm_z partials (z=0..3, STG) + S_ab (z=4) ========  [R12-identical]
// 128 thr; gemm tile 32(M)x64(N), K=256 ; grid (32, 8, 5)
__global__ __launch_bounds__(128) void gemm_z_kernel(const float* __restrict__ x, const float* __restrict__ hx,
                              const float* __restrict__ Wih, const float* __restrict__ Whh) {
    int tid = threadIdx.x;
    int zid = blockIdx.z;

    if (zid == 4) {
        int sub = tid >> 6;
        int lane = tid & 63;
        int j = ((blockIdx.y * 32 + blockIdx.x) << 1) | sub;   // 0..511
        const float* w0 = Wih + (0 * HH + j) * DI;
        const float* w1 = Wih + (1 * HH + j) * DI;
        const float* w2 = Wih + (2 * HH + j) * DI;
        float s[6] = {0.f, 0.f, 0.f, 0.f, 0.f, 0.f};
        for (int d = lane; d < DI; d += 64) {
            float a = w0[d], b = w1[d], c = w2[d];
            s[0] += a * a; s[1] += a * b; s[2] += a * c;
            s[3] += b * b; s[4] += b * c; s[5] += c * c;
        }
        __shared__ float red[2][2][6];
        int w = lane >> 5;
        #pragma unroll
        for (int q = 0; q < 6; q++) {
            float v = s[q];
            #pragma unroll
            for (int o = 16; o > 0; o >>= 1) v += __shfl_xor_sync(0xffffffffu, v, o);
            if ((lane & 31) == 0) red[sub][w][q] = v;
        }
        __syncthreads();
        if (lane == 0) {
            #pragma unroll
            for (int q = 0; q < 6; q++)
                g_S6[q * HH + j] = red[sub][0][q] + red[sub][1][q];
        }
        return;
    }

    __shared__ float As[2][16][36];
    __shared__ float Bs[2][16][68];
    int tx = tid % 16, ty = tid / 16;
    int lr = tid / 4, lc = (tid % 4) * 4;
    int br = tid / 2, bkc = (tid % 2) * 8;
    const float* A = (zid >> 1) ? hx : x;
    const float* B = (zid >> 1) ? Whh : Wih;
    int k0base = (zid & 1) * 256;
    int nbase = blockIdx.y * 32;
    int mbase = blockIdx.x * 64;
    float acc[4][4] = {};
    const float* Arow = A + (nbase + lr) * 512 + k0base;
    const float* Brow = B + (mbase + br) * 512 + k0base;

    {
        float4 ra = *(const float4*)(Arow + lc);
        As[0][lc + 0][lr] = ra.x; As[0][lc + 1][lr] = ra.y; As[0][lc + 2][lr] = ra.z; As[0][lc + 3][lr] = ra.w;
        float4 rb0 = *(const float4*)(Brow + bkc);
        float4 rb1 = *(const float4*)(Brow + bkc + 4);
        Bs[0][bkc + 0][br] = rb0.x; Bs[0][bkc + 1][br] = rb0.y; Bs[0][bkc + 2][br] = rb0.z; Bs[0][bkc + 3][br] = rb0.w;
        Bs[0][bkc + 4][br] = rb1.x; Bs[0][bkc + 5][br] = rb1.y; Bs[0][bkc + 6][br] = rb1.z; Bs[0][bkc + 7][br] = rb1.w;
    }
    __syncthreads();

    for (int s = 0; s < 16; s++) {
        int cur = s & 1;
        bool nx = (s + 1 < 16);
        float4 na, nb0, nb1;
        if (nx) {
            int k0 = (s + 1) * 16;
            na  = *(const float4*)(Arow + k0 + lc);
            nb0 = *(const float4*)(Brow + k0 + bkc);
            nb1 = *(const float4*)(Brow + k0 + bkc + 4);
        }
        #pragma unroll
        for (int kk = 0; kk < 16; kk++) {
            float4 a4 = *(const float4*)&As[cur][kk][ty * 4];
            float4 b4 = *(const float4*)&Bs[cur][kk][tx * 4];
            FMA16();
        }
        if (nx) {
            int nb_ = cur ^ 1;
            As[nb_][lc + 0][lr] = na.x; As[nb_][lc + 1][lr] = na.y; As[nb_][lc + 2][lr] = na.z; As[nb_][lc + 3][lr] = na.w;
            Bs[nb_][bkc + 0][br] = nb0.x; Bs[nb_][bkc + 1][br] = nb0.y; Bs[nb_][bkc + 2][br] = nb0.z; Bs[nb_][bkc + 3][br] = nb0.w;
            Bs[nb_][bkc + 4][br] = nb1.x; Bs[nb_][bkc + 5][br] = nb1.y; Bs[nb_][bkc + 6][br] = nb1.z; Bs[nb_][bkc + 7][br] = nb1.w;
        }
        __syncthreads();
    }
    float* outp = g_Zp + zid * (NB * H4);
    #pragma unroll
    for (int i = 0; i < 4; i++) {
        int row = nbase + ty * 4 + i;
        #pragma unroll
        for (int jj = 0; jj < 4; jj++) {
            outp[row * H4 + mbase + tx * 4 + jj] = acc[i][jj];
        }
    }
}

// ---------------- gates: activations, h_new, coeffs, diag, CG init; zero g_t ----------------
__global__ void gates_kernel(const float* __restrict__ cx,
                             const float* __restrict__ bih, const float* __restrict__ bhh,
                             float* __restrict__ out_h, float* __restrict__ out_x) {
    int n = blockIdx.x, j = threadIdx.x;  // 256 x 512
    const float* z0 = g_Zp + 0 * NB * H4 + n * H4;
    const float* z1 = g_Zp + 1 * NB * H4 + n * H4;
    const float* z2 = g_Zp + 2 * NB * H4 + n * H4;
    const float* z3 = g_Zp + 3 * NB * H4 + n * H4;
    #define ZSUM(o) (z0[o] + z1[o] + z2[o] + z3[o] + bih[o] + bhh[o])
    float zi = ZSUM(j);
    float zf = ZSUM(HH + j);
    float zg = ZSUM(2 * HH + j);
    float zo = ZSUM(3 * HH + j);
    float iv = 1.f / (1.f + expf(-zi));
    float fv = 1.f / (1.f + expf(-zf));
    float gv = tanhf(zg);
    float ov = 1.f / (1.f + expf(-zo));
    float cxv = cx[n * HH + j];
    float cn = fv * cxv + iv * gv;
    out_h[n * HH + j] = ov * tanhf(cn);

    float c0 = iv * (1.f - iv) * gv;
    float c1 = fv * (1.f - fv) * cxv;
    float c2 = (1.f - gv * gv) * iv;
    g_C3[n * H3 + j] = c0;
    g_C3[n * H3 + HH + j] = c1;
    g_C3[n * H3 + 2 * HH + j] = c2;

    float s00 = g_S6[j], s01 = g_S6[HH + j], s02 = g_S6[2 * HH + j];
    float s11 = g_S6[3 * HH + j], s12 = g_S6[4 * HH + j], s22 = g_S6[5 * HH + j];
    float dg = 1.f + EPSV * (c0 * c0 * s00 + c1 * c1 * s11 + c2 * c2 * s22 +
                             2.f * (c0 * c1 * s01 + c0 * c2 * s02 + c1 * c2 * s12));
    g_diagA[n * HH + j] = dg;

    out_x[n * HH + j] = 0.f;
    g_t[n * DI + j] = 0.f;              // zero accumulation target for first k1
    float rj = cn;
    float zj = rj / dg;
    g_r[n * HH + j] = rj;
    g_p[n * HH + j] = zj;
    g_u[n * H3 + j] = c0 * zj;
    g_u[n * H3 + HH + j] = c1 * zj;
    g_u[n * H3 + 2 * HH + j] = c2 * zj;

    __shared__ float red[512];
    red[j] = rj * zj;
    __syncthreads();
    for (int s = 256; s > 0; s >>= 1) {
        if (j < s) red[j] += red[j + s];
        __syncthreads();
    }
    if (j == 0) g_rz[n] = red[0];
}

// ======== k1: g_t += u-slice @ W-slice (NN) via RED.ADD ========  [R12-identical]
// 128 thr, tile 32x64, K=256 ; grid (8, 8, 6) -> 384 CTAs
__global__ __launch_bounds__(128) void k1_kernel(const float* __restrict__ Wih) {
    __shared__ float As[2][16][36];
    __shared__ float Bs[2][16][68];
    int tid = threadIdx.x;
    int tx = tid % 16, ty = tid / 16;
    int lr = tid / 4, lc = (tid % 4) * 4;
    int bkr = tid / 16, bc = (tid % 16) * 4;
    int zid = blockIdx.z;
    int gate = zid >> 1, kh = zid & 1;
    int jbase = gate * HH + kh * 256;
    int nbase = blockIdx.y * 32;
    int dbase = blockIdx.x * 64;
    float acc[4][4] = {};

    const float* Arow = g_u + (nbase + lr) * H3 + jbase;
    const float* Bb = Wih + jbase * DI + dbase;

    {
        float4 ra = *(const float4*)(Arow + lc);
        As[0][lc + 0][lr] = ra.x; As[0][lc + 1][lr] = ra.y; As[0][lc + 2][lr] = ra.z; As[0][lc + 3][lr] = ra.w;
        *(float4*)&Bs[0][bkr][bc]     = *(const float4*)(Bb + bkr * DI + bc);
        *(float4*)&Bs[0][bkr + 8][bc] = *(const float4*)(Bb + (bkr + 8) * DI + bc);
    }
    __syncthreads();

    for (int s = 0; s < 16; s++) {
        int cur = s & 1;
        bool nx = (s + 1 < 16);
        float4 na, nb0, nb1;
        if (nx) {
            int k0 = (s + 1) * 16;
            na  = *(const float4*)(Arow + k0 + lc);
            nb0 = *(const float4*)(Bb + (k0 + bkr) * DI + bc);
            nb1 = *(const float4*)(Bb + (k0 + bkr + 8) * DI + bc);
        }
        #pragma unroll
        for (int kk = 0; kk < 16; kk++) {
            float4 a4 = *(const float4*)&As[cur][kk][ty * 4];
            float4 b4 = *(const float4*)&Bs[cur][kk][tx * 4];
            FMA16();
        }
        if (nx) {
            int nbuf = cur ^ 1;
            As[nbuf][lc + 0][lr] = na.x; As[nbuf][lc + 1][lr] = na.y; As[nbuf][lc + 2][lr] = na.z; As[nbuf][lc + 3][lr] = na.w;
            *(float4*)&Bs[nbuf][bkr][bc] = nb0;
            *(float4*)&Bs[nbuf][bkr + 8][bc] = nb1;
        }
        __syncthreads();
    }
    #pragma unroll
    for (int i = 0; i < 4; i++) {
        int row = nbase + ty * 4 + i;
        float* tr = g_t + row * DI + dbase + tx * 4;
        atomicAdd(tr + 0, acc[i][0]);
        atomicAdd(tr + 1, acc[i][1]);
        atomicAdd(tr + 2, acc[i][2]);
        atomicAdd(tr + 3, acc[i][3]);
    }
}

// ======== k2: vp[kh] = t @ W3^T-slice (NT) ========  [R12-identical]
// 128 thr, tile 32x64, K=256 ; grid (24, 8, 2) -> 384 CTAs
__global__ __launch_bounds__(128) void k2_kernel(const float* __restrict__ Wih) {
    __shared__ float As[2][16][36];
    __shared__ float Bs[2][16][68];
    int tid = threadIdx.x;
    int tx = tid % 16, ty = tid / 16;
    int lr = tid / 4, lc = (tid % 4) * 4;
    int br = tid / 2, bkc = (tid % 2) * 8;
    int kh = blockIdx.z;
    int dbase0 = kh * 256;
    int nbase = blockIdx.y * 32;
    int mbase = blockIdx.x * 64;
    float acc[4][4] = {};

    const float* T = g_t + (nbase + lr) * DI + dbase0;
    const float* Brow = Wih + (mbase + br) * DI + dbase0;

    {
        float4 ta = *(const float4*)(T + lc);
        As[0][lc + 0][lr] = ta.x; As[0][lc + 1][lr] = ta.y; As[0][lc + 2][lr] = ta.z; As[0][lc + 3][lr] = ta.w;
        float4 rb0 = *(const float4*)(Brow + bkc);
        float4 rb1 = *(const float4*)(Brow + bkc + 4);
        Bs[0][bkc + 0][br] = rb0.x; Bs[0][bkc + 1][br] = rb0.y; Bs[0][bkc + 2][br] = rb0.z; Bs[0][bkc + 3][br] = rb0.w;
        Bs[0][bkc + 4][br] = rb1.x; Bs[0][bkc + 5][br] = rb1.y; Bs[0][bkc + 6][br] = rb1.z; Bs[0][bkc + 7][br] = rb1.w;
    }
    __syncthreads();

    for (int s = 0; s < 16; s++) {
        int cur = s & 1;
        bool nx = (s + 1 < 16);
        float4 ta, nb0, nb1;
        if (nx) {
            int k0 = (s + 1) * 16;
            ta  = *(const float4*)(T + k0 + lc);
            nb0 = *(const float4*)(Brow + k0 + bkc);
            nb1 = *(const float4*)(Brow + k0 + bkc + 4);
        }
        #pragma unroll
        for (int kk = 0; kk < 16; kk++) {
            float4 a4 = *(const float4*)&As[cur][kk][ty * 4];
            float4 b4 = *(const float4*)&Bs[cur][kk][tx * 4];
            FMA16();
        }
        if (nx) {
            int nbuf = cur ^ 1;
            As[nbuf][lc + 0][lr] = ta.x; As[nbuf][lc + 1][lr] = ta.y; As[nbuf][lc + 2][lr] = ta.z; As[nbuf][lc + 3][lr] = ta.w;
            Bs[nbuf][bkc + 0][br] = nb0.x; Bs[nbuf][bkc + 1][br] = nb0.y; Bs[nbuf][bkc + 2][br] = nb0.z; Bs[nbuf][bkc + 3][br] = nb0.w;
            Bs[nbuf][bkc + 4][br] = nb1.x; Bs[nbuf][bkc + 5][br] = nb1.y; Bs[nbuf][bkc + 6][br] = nb1.z; Bs[nbuf][bkc + 7][br] = nb1.w;
        }
        __syncthreads();
    }
    float* outp = g_vp + kh * (NB * H3);
    #pragma unroll
    for (int i = 0; i < 4; i++) {
        int row = nbase + ty * 4 + i;
        #pragma unroll
        for (int jj = 0; jj < 4; jj++) {
            outp[row * H3 + mbase + tx * 4 + jj] = acc[i][jj];
        }
    }
}

// ---------------- full PCG update (non-final iterations); re-zeroes g_t ----------------
__global__ __launch_bounds__(256) void cg_update_kernel(float* __restrict__ out_x) {
    int n = blockIdx.x;
    int t = threadIdx.x;
    int j0 = t, j1 = t + 256;
    __shared__ float warpsum[8];
    __shared__ float s_scalar;

    const float* v0 = g_vp + n * H3;
    const float* v1 = g_vp + NB * H3 + n * H3;
    const float* C = g_C3 + n * H3;

    // zero g_t for the next k1 accumulation (t consumed by k2 already)
    g_t[n * DI + j0] = 0.f;
    g_t[n * DI + j1] = 0.f;

    float p0 = g_p[n * HH + j0], p1 = g_p[n * HH + j1];
    float c00 = C[j0], c10 = C[HH + j0], c20 = C[2 * HH + j0];
    float c01 = C[j1], c11 = C[HH + j1], c21 = C[2 * HH + j1];
    float gp0 = c00 * (v0[j0] + v1[j0]) + c10 * (v0[HH + j0] + v1[HH + j0]) + c20 * (v0[2 * HH + j0] + v1[2 * HH + j0]);
    float gp1 = c01 * (v0[j1] + v1[j1]) + c11 * (v0[HH + j1] + v1[HH + j1]) + c21 * (v0[2 * HH + j1] + v1[2 * HH + j1]);
    float Ap0 = p0 + EPSV * gp0;
    float Ap1 = p1 + EPSV * gp1;

    float part = p0 * Ap0 + p1 * Ap1;
    #pragma unroll
    for (int o = 16; o > 0; o >>= 1) part += __shfl_xor_sync(0xffffffffu, part, o);
    if ((t & 31) == 0) warpsum[t >> 5] = part;
    __syncthreads();
    if (t < 8) {
        float v = warpsum[t];
        #pragma unroll
        for (int o = 4; o > 0; o >>= 1) v += __shfl_xor_sync(0xffu, v, o);
        if (t == 0) s_scalar = v;
    }
    __syncthreads();
    float rzold = g_rz[n];
    float alpha = rzold / fmaxf(s_scalar, 1e-30f);

    float x0 = out_x[n * HH + j0] + alpha * p0;
    float x1 = out_x[n * HH + j1] + alpha * p1;
    float r0 = g_r[n * HH + j0] - alpha * Ap0;
    float r1 = g_r[n * HH + j1] - alpha * Ap1;
    float z0 = r0 / g_diagA[n * HH + j0];
    float z1 = r1 / g_diagA[n * HH + j1];

    __syncthreads();
    part = r0 * z0 + r1 * z1;
    #pragma unroll
    for (int o = 16; o > 0; o >>= 1) part += __shfl_xor_sync(0xffffffffu, part, o);
    if ((t & 31) == 0) warpsum[t >> 5] = part;
    __syncthreads();
    if (t < 8) {
        float v = warpsum[t];
        #pragma unroll
        for (int o = 4; o > 0; o >>= 1) v += __shfl_xor_sync(0xffu, v, o);
        if (t == 0) { s_scalar = v; g_rz[n] = v; }
    }
    __syncthreads();
    float beta = s_scalar / fmaxf(rzold, 1e-30f);

    float pn0 = z0 + beta * p0;
    float pn1 = z1 + beta * p1;
    out_x[n * HH + j0] = x0;  out_x[n * HH + j1] = x1;
    g_r[n * HH + j0] = r0;    g_r[n * HH + j1] = r1;
    g_p[n * HH + j0] = pn0;   g_p[n * HH + j1] = pn1;
    float* U = g_u + n * H3;
    U[j0] = c00 * pn0;           U[j1] = c01 * pn1;
    U[HH + j0] = c10 * pn0;      U[HH + j1] = c11 * pn1;
    U[2 * HH + j0] = c20 * pn0;  U[2 * HH + j1] = c21 * pn1;
}

// ---------------- final PCG step: pAp = |p|^2 + eps*|t|^2 ; x += alpha*p (no k2 needed) ----------------
__global__ __launch_bounds__(256) void cg_final_kernel(float* __restrict__ out_x) {
    int n = blockIdx.x;
    int t = threadIdx.x;
    int j0 = t, j1 = t + 256;
    __shared__ float warpsum[8];
    __shared__ float s_scalar;

    float p0 = g_p[n * HH + j0], p1 = g_p[n * HH + j1];
    float t0 = g_t[n * DI + j0], t1 = g_t[n * DI + j1];

    float part = (p0 * p0 + p1 * p1) + EPSV * (t0 * t0 + t1 * t1);
    #pragma unroll
    for (int o = 16; o > 0; o >>= 1) part += __shfl_xor_sync(0xffffffffu, part, o);
    if ((t & 31) == 0) warpsum[t >> 5] = part;
    __syncthreads();
    if (t < 8) {
        float v = warpsum[t];
        #pragma unroll
        for (int o = 4; o > 0; o >>= 1) v += __shfl_xor_sync(0xffu, v, o);
        if (t == 0) s_scalar = v;
    }
    __syncthreads();
    float alpha = g_rz[n] / fmaxf(s_scalar, 1e-30f);

    out_x[n * HH + j0] += alpha * p0;
    out_x[n * HH + j1] += alpha * p1;
}

// ---------------- launch ----------------
extern "C" void kernel_launch(void* const* d_in, const int* in_sizes, int n_in,
                              void* d_out, int out_size) {
    const float* x   = (const float*)d_in[0];
    const float* hx  = (const float*)d_in[1];
    const float* cx  = (const float*)d_in[2];
    const float* Wih = (const float*)d_in[3];
    const float* Whh = (const float*)d_in[4];
    const float* bih = (const float*)d_in[5];
    const float* bhh = (const float*)d_in[6];
    float* out_h = (float*)d_out;
    float* out_x = out_h + NB * HH;

    gemm_z_kernel<<<dim3(H4 / 64, NB / 32, 5), 128>>>(x, hx, Wih, Whh);
    gates_kernel<<<NB, HH>>>(cx, bih, bhh, out_h, out_x);

    for (int it = 0; it < NITER; it++) {
        k1_kernel<<<dim3(DI / 64, NB / 32, 6), 128>>>(Wih);
        if (it < NITER - 1) {
            k2_kernel<<<dim3(H3 / 64, NB / 32, 2), 128>>>(Wih);
            cg_update_kernel<<<NB, 256>>>(out_x);
        } else {
            // final iteration: alpha needs only |p|^2 + eps*|t|^2 — skip k2 entirely
            cg_final_kernel<<<NB, 256>>>(out_x);
        }
    }
}